// round 9
// baseline (speedup 1.0000x reference)
#include <cuda_runtime.h>
#include <cuda_bf16.h>
#include <cstdint>
#include <cstdio>

// BinTokenizer: tokens = searchsorted(linspace(0,1,257), clip(x,1e-6,1-1e-6),
// 'right') - 1  ==  floor(clip(x)*256)  (exact in fp32).
//
// R8 EXPERIMENT: four different kernels all returned rel_err == 1.0 exactly ->
// kernel-side read/size theories falsified by insensitivity. Surviving theory:
// the harness's __output__ dtype is float32, so int32 token writes are read
// back as denormal floats ~ 0 -> ||0-ref||/||ref|| == 1.0 exactly, no matter
// what we do. This round writes tokens as FLOAT values (0.0f..255.0f):
//   * if output dtype is fp32 -> exact match -> PASS (~150-185 us, HBM-bound)
//   * if output dtype is int32 -> rel_err ~1e7 (distinct from 1.0) -> theory
//     falsified with signal; stderr dump of sizes gives ground truth for R9.

#define N_BINS 256
#define EPS 1e-6f

__device__ __forceinline__ float tok1f(float x) {
    x = fminf(fmaxf(x, EPS), 1.0f - EPS);
    float t = floorf(x * 256.0f);                 // exact: *2^8, then floor
    return fminf(fmaxf(t, 0.0f), 255.0f);         // safety clamp
}

__global__ void __launch_bounds__(256)
bin_tokenizer_kernel(const float4* __restrict__ in, float4* __restrict__ out,
                     long long n4) {
    const long long stride = (long long)gridDim.x * blockDim.x;
    for (long long i = (long long)blockIdx.x * blockDim.x + threadIdx.x;
         i < n4; i += stride) {
        float4 v = in[i];
        float4 t;
        t.x = tok1f(v.x);
        t.y = tok1f(v.y);
        t.z = tok1f(v.z);
        t.w = tok1f(v.w);
        out[i] = t;
    }
}

__global__ void bin_tokenizer_tail(const float* __restrict__ in,
                                   float* __restrict__ out,
                                   long long start, long long n) {
    long long i = start + (long long)blockIdx.x * blockDim.x + threadIdx.x;
    if (i < n) out[i] = tok1f(in[i]);
}

extern "C" void kernel_launch(void* const* d_in, const int* in_sizes, int n_in,
                              void* d_out, int out_size) {
    // Diagnostics: host-side only, no CUDA API, graph-capture safe. Shows up
    // in the bench error/log on failure and settles the metadata questions.
    fprintf(stderr, "[ktrace] n_in=%d out_size=%d", n_in, out_size);
    for (int i = 0; i < n_in && i < 8; i++)
        fprintf(stderr, " in_sizes[%d]=%d", i, in_sizes[i]);
    fprintf(stderr, "\n");

    // inputs = largest buffer (ordering-proof).
    int xi = 0, ti = 0;
    for (int i = 1; i < n_in; i++) {
        if (in_sizes[i] > in_sizes[xi]) xi = i;
        if (in_sizes[i] < in_sizes[ti]) ti = i;
    }
    const long long nx_raw = (long long)in_sizes[xi];
    const long long nt_raw = (long long)in_sizes[ti];
    const long long os     = (long long)out_size;

    // Units detection via the 257-entry thresholds buffer (257 elements vs
    // 1028 bytes), with a ratio cross-check; default to elements per contract.
    int scale;
    if      (nt_raw == (long long)(N_BINS + 1))      scale = 1;
    else if (nt_raw == 4LL * (N_BINS + 1))           scale = 4;
    else if (nx_raw == 4LL * os)                     scale = 4;
    else                                             scale = 1;

    long long n = nx_raw / scale;                 // element count of inputs

    // Output capacity guard under either interpretation of out_size.
    long long out_cap;
    if (os == n || os == 4LL * n) out_cap = n;
    else                          out_cap = (os < n) ? os : n;
    if (out_cap < n) n = out_cap;

    const float* in = (const float*)d_in[xi];
    float* out = (float*)d_out;
    long long n4 = n >> 2;

    if (n4 > 0) {
        const int threads = 256;
        long long want = (n4 + threads - 1) / threads;
        int blocks = (want > 118400) ? 118400 : (int)want;  // grid-stride cap
        bin_tokenizer_kernel<<<blocks, threads>>>(
            (const float4*)in, (float4*)out, n4);
    }
    long long done = n4 << 2;
    if (done < n) {
        int rem = (int)(n - done);
        bin_tokenizer_tail<<<(rem + 255) / 256, 256>>>(in, out, done, n);
    }
}

// round 13
// speedup vs baseline: 1.0810x; 1.0810x over previous
#include <cuda_runtime.h>
#include <cuda_bf16.h>
#include <cstdint>

// BinTokenizer: tokens = searchsorted(linspace(0,1,257), clip(x,1e-6,1-1e-6),
// 'right') - 1 == floor(clip(x)*256) (exact in fp32). Output dtype is FLOAT32
// (confirmed R9: int writes read back as denormals -> rel_err 1.0; float token
// values give rel_err 0.0). Tokens 0..255 are exact in fp32.
//
// R10 perf pass: flat launch (no grid-stride loop), 2x float4 per thread,
// 32-bit indexing, streaming cache hints, minimal fp ops (final clamp removed:
// clip guarantees floor(x*256) in [0,255]).

#define N_BINS 256
#define EPS 1e-6f

__device__ __forceinline__ float tok1f(float x) {
    x = fminf(fmaxf(x, EPS), 1.0f - EPS);
    return floorf(x * 256.0f);        // in [0,255] by construction
}

__device__ __forceinline__ float4 tok4(float4 v) {
    float4 t;
    t.x = tok1f(v.x); t.y = tok1f(v.y);
    t.z = tok1f(v.z); t.w = tok1f(v.w);
    return t;
}

// Each block covers 512 float4s: thread t handles indices base+t and base+t+256.
__global__ void __launch_bounds__(256)
bin_tokenizer_kernel(const float4* __restrict__ in, float4* __restrict__ out,
                     unsigned n4) {
    unsigned i0 = blockIdx.x * 512u + threadIdx.x;
    unsigned i1 = i0 + 256u;
    if (i1 < n4) {                    // fast path: both in range (steady state)
        float4 a = __ldcs(in + i0);   // front-batched loads -> MLP 2
        float4 b = __ldcs(in + i1);
        __stcs(out + i0, tok4(a));
        __stcs(out + i1, tok4(b));
    } else if (i0 < n4) {
        float4 a = __ldcs(in + i0);
        __stcs(out + i0, tok4(a));
    }
}

__global__ void bin_tokenizer_tail(const float* __restrict__ in,
                                   float* __restrict__ out,
                                   long long start, long long n) {
    long long i = start + (long long)blockIdx.x * blockDim.x + threadIdx.x;
    if (i < n) out[i] = tok1f(in[i]);
}

extern "C" void kernel_launch(void* const* d_in, const int* in_sizes, int n_in,
                              void* d_out, int out_size) {
    // inputs = largest buffer; thresholds = smallest (units inference only).
    int xi = 0, ti = 0;
    for (int i = 1; i < n_in; i++) {
        if (in_sizes[i] > in_sizes[xi]) xi = i;
        if (in_sizes[i] < in_sizes[ti]) ti = i;
    }
    const long long nx_raw = (long long)in_sizes[xi];
    const long long nt_raw = (long long)in_sizes[ti];
    const long long os     = (long long)out_size;

    // Units detection (unchanged from the passing R9 kernel).
    int scale;
    if      (nt_raw == (long long)(N_BINS + 1))      scale = 1;
    else if (nt_raw == 4LL * (N_BINS + 1))           scale = 4;
    else if (nx_raw == 4LL * os)                     scale = 4;
    else                                             scale = 1;

    long long n = nx_raw / scale;

    long long out_cap;
    if (os == n || os == 4LL * n) out_cap = n;
    else                          out_cap = (os < n) ? os : n;
    if (out_cap < n) n = out_cap;

    const float* in = (const float*)d_in[xi];
    float* out = (float*)d_out;
    long long n4 = n >> 2;

    if (n4 > 0) {
        unsigned blocks = (unsigned)((n4 + 511) / 512);   // 512 float4s / block
        bin_tokenizer_kernel<<<blocks, 256>>>(
            (const float4*)in, (float4*)out, (unsigned)n4);
    }
    long long done = n4 << 2;
    if (done < n) {
        int rem = (int)(n - done);
        bin_tokenizer_tail<<<(rem + 255) / 256, 256>>>(in, out, done, n);
    }
}